// round 12
// baseline (speedup 1.0000x reference)
#include <cuda_runtime.h>
#include <cuda_bf16.h>
#include <cuda_fp16.h>

#define BB 64
#define SS 512
#define EE 512
#define AA 256
#define HP 256
#define PP 128
#define DD 1024
#define MM 128
#define TT 800
#define G3 3072
#define NB 128
#define NBL 148
#define TPB 512
#define KT2 2688
#define NCHT 26
#define WBLOB 768          /* uint2 per W chunk blob (fp16) */

// dynamic smem layout (float words)
#define O_WP  0                         /* 13 resident W blobs: 13*1536 */
#define O_A   19968                     /* 8 A slots: 8*2304 */
#define O_DPS 38400
#define O_VS  38656
#define O_AWS 38912
#define O_ATTR 39424
#define O_SM2 39488
#define O_WDS 41536
#define O_HS  43584
#define SMEM_WORDS 44096                /* 176,384 bytes */

// ---------------- static scratch ----------------
__device__ __align__(128) __half g_epH[BB*SS*AA];
__device__ __align__(128) __half g_encH[BB*SS*EE];
__device__ __align__(128) float g_prev[TT*BB*MM];
__device__ __align__(128) float g_ph  [TT*BB*HP];
__device__ __align__(128) float g_pre [TT*BB*PP];
__device__ __align__(128) float g_h   [BB*DD];
__device__ __align__(128) float g_sc  [BB*SS];
__device__ __align__(128) float g_dpp [BB*NB*AA];
__device__ __align__(128) __half g_Af [BB*KT2];
__device__ __align__(128) uint2 g_Wf2[(size_t)64*NCHT*WBLOB];
__device__ __align__(128) float g_gp  [NB*4*64*16];
__device__ __align__(128) float g_Hb  [(size_t)TT*BB*DD];
__device__ __align__(128) float g_Cb  [(size_t)TT*BB*EE];
__device__ __align__(128) volatile unsigned g_flags[NBL*32];
__device__ __align__(128) volatile unsigned g_pairf[NBL*32];
__device__ __align__(128) volatile unsigned g_attf[NB*32];
__device__ volatile unsigned g_rel;

__device__ __forceinline__ float fsig(float x){
    float e = __expf(-x);
    return __fdividef(1.f, 1.f + e);
}
__device__ __forceinline__ float ftanh(float x){
    x = fminf(fmaxf(x, -15.f), 15.f);
    float e = __expf(2.f*x);
    return __fdividef(e - 1.f, e + 1.f);
}
__device__ __forceinline__ float tanh_mufu(float x){
    float y; asm("tanh.approx.f32 %0, %1;" : "=f"(y) : "f"(x)); return y;
}

__device__ __forceinline__ void gsync(unsigned &gen){
    gen++;
    __syncthreads();
    const int tid = threadIdx.x;
    if (blockIdx.x == 0){
        if (tid > 0 && tid < NBL){
            while (g_flags[tid*32] < gen) {}
        }
        __syncthreads();
        if (tid == 0){ __threadfence(); g_rel = gen; }
    } else {
        if (tid == 0){
            __threadfence();
            g_flags[blockIdx.x*32] = gen;
            while (g_rel < gen) {}
            __threadfence();
        }
    }
    __syncthreads();
}

__device__ __forceinline__ void psync(unsigned &gen){
    gen++;
    __syncthreads();
    if (threadIdx.x == 0){
        __threadfence();
        g_pairf[blockIdx.x*32] = gen;
        while (g_pairf[(blockIdx.x^1)*32] < gen) {}
        __threadfence();
    }
    __syncthreads();
}

#define BAR1 asm volatile("bar.sync 1, 128;" ::: "memory")
#define BAR2 asm volatile("bar.sync 2, 384;" ::: "memory")

__device__ __forceinline__ void cp16(unsigned dst, const void* src){
    asm volatile("cp.async.cg.shared.global [%0], [%1], 16;" :: "r"(dst), "l"(src) : "memory");
}
#define CP_COMMIT() asm volatile("cp.async.commit_group;" ::: "memory")
#define CPW(n) asm volatile("cp.async.wait_group " #n ";" ::: "memory")

#define MMA(D0,D1,D2,D3,A0,A1,A2,A3,B0,B1) \
    asm volatile("mma.sync.aligned.m16n8k16.row.col.f32.f16.f16.f32 " \
        "{%0,%1,%2,%3},{%4,%5,%6,%7},{%8,%9},{%0,%1,%2,%3};" \
        : "+f"(D0),"+f"(D1),"+f"(D2),"+f"(D3) \
        : "r"(A0),"r"(A1),"r"(A2),"r"(A3),"r"(B0),"r"(B1))

#define DO_MMA(ACC, slot, wslot) { \
    const unsigned* A32 = smu + O_A + (slot)*2304; \
    const uint2* Wq = (const uint2*)(smu + O_WP + (wslot)*1536) + nt*256; \
    _Pragma("unroll") \
    for (int kl = 0; kl < 4; kl++){ \
        const int r0 = (m0+g)*36 + kl*8 + tig; \
        unsigned a0 = A32[r0],   a1 = A32[r0+288]; \
        unsigned a2 = A32[r0+4], a3 = A32[r0+292]; \
        _Pragma("unroll") \
        for (int j = 0; j < 2; j++){ \
            uint2 bw = Wq[j*128 + kl*32 + lane]; \
            MMA(ACC[j][0],ACC[j][1],ACC[j][2],ACC[j][3], a0,a1,a2,a3, bw.x,bw.y); \
        } \
    } }

#define H_ITER(i, WLIT) { \
    CPW(WLIT); \
    BAR2; \
    if (nt == 2){ DO_MMA(aH, (i), 5+(i)); } else { DO_MMA(aX, (i), 5+(i)); } }

#define X_ITER(j, WLIT) { \
    CPW(WLIT); \
    BAR2; \
    DO_MMA(aX, (j), (j)); }

// stage one chunk's A plane (8KB) into slot; called by warps 0-11 (384 threads)
__device__ __forceinline__ void stage_A(unsigned sbase, int slot, int idx4, int tid){
    #pragma unroll
    for (int k = 0; k < 2; k++){
        int idx = tid + k*384;
        if (idx < 512){
            int row = idx >> 3, col = idx & 7;
            cp16(sbase + (O_A + slot*2304 + (row*9+col)*4)*4,
                 (const uint4*)g_Af + row*336 + idx4 + col);
        }
    }
    CP_COMMIT();
}

// ---------------- generic tiled SGEMM (pre/epilogue only) ----------------
#define BKK 16
__global__ void sgemm(const float* __restrict__ A, const float* __restrict__ B,
                      const float* __restrict__ bias, float* __restrict__ C,
                      int M, int N, int K, int flags, int Bdim, int Tdim)
{
    __shared__ float As[BKK][64];
    __shared__ float Bs[BKK][64];
    const int n0 = blockIdx.x * 64;
    const int m0 = blockIdx.y * 64;
    const int tid = threadIdx.x;
    const int tx = tid & 15;
    const int ty = tid >> 4;
    float acc[4][4] = {};
    const int arow  = tid >> 2;
    const int acol4 = (tid & 3) * 4;
    const int brow  = tid >> 4;
    const int bcol4 = (tid & 15) * 4;

    for (int k = 0; k < K; k += BKK) {
        float4 av = *(const float4*)(A + (size_t)(m0 + arow) * K + k + acol4);
        As[acol4+0][arow] = av.x;
        As[acol4+1][arow] = av.y;
        As[acol4+2][arow] = av.z;
        As[acol4+3][arow] = av.w;
        float4 bvv = *(const float4*)(B + (size_t)(k + brow) * N + n0 + bcol4);
        *(float4*)(&Bs[brow][bcol4]) = bvv;
        __syncthreads();
        #pragma unroll
        for (int kk = 0; kk < BKK; kk++) {
            float4 a4 = *(const float4*)(&As[kk][ty*4]);
            float4 b4 = *(const float4*)(&Bs[kk][tx*4]);
            acc[0][0] += a4.x*b4.x; acc[0][1] += a4.x*b4.y; acc[0][2] += a4.x*b4.z; acc[0][3] += a4.x*b4.w;
            acc[1][0] += a4.y*b4.x; acc[1][1] += a4.y*b4.y; acc[1][2] += a4.y*b4.z; acc[1][3] += a4.y*b4.w;
            acc[2][0] += a4.z*b4.x; acc[2][1] += a4.z*b4.y; acc[2][2] += a4.z*b4.z; acc[2][3] += a4.z*b4.w;
            acc[3][0] += a4.w*b4.x; acc[3][1] += a4.w*b4.y; acc[3][2] += a4.w*b4.z; acc[3][3] += a4.w*b4.w;
        }
        __syncthreads();
    }
    #pragma unroll
    for (int i = 0; i < 4; i++) {
        const int m = m0 + ty*4 + i;
        #pragma unroll
        for (int j = 0; j < 4; j++) {
            const int n = n0 + tx*4 + j;
            float val = acc[i][j];
            if (bias) val += bias[n];
            if (flags & 1) val = fmaxf(val, 0.f);
            size_t idx;
            if (Bdim > 0) {
                const int bq = m % Bdim, tq = m / Bdim;
                idx = ((size_t)bq * Tdim + tq) * N + n;
            } else {
                idx = (size_t)m * N + n;
            }
            if (flags & 4)      ((__half*)C)[idx] = __float2half_rn(val);
            else if (flags & 2) C[idx] += val;
            else                C[idx] = val;
        }
    }
}

__global__ void k_init(){
    int i = blockIdx.x*256 + threadIdx.x;
    if (i < BB*NB*AA) g_dpp[i] = 0.f;
    if (i < BB*KT2) g_Af[i] = __float2half_rn(0.f);
    if (i < BB*DD) g_h[i] = 0.f;
}

__global__ void k_prev(const float* __restrict__ tm){
    int i = blockIdx.x*256 + threadIdx.x;
    if (i >= TT*BB*MM) return;
    int m  = i & (MM-1);
    int tb = i >> 7;
    int b  = tb & (BB-1);
    int t  = tb >> 6;
    g_prev[i] = (t == 0) ? 0.f : tm[((size_t)b*TT + (t-1))*MM + m];
}

__global__ void k_convE(const float* __restrict__ enc){
    int i = blockIdx.x*256 + threadIdx.x;
    if (i < BB*SS*EE) g_encH[i] = __float2half_rn(enc[i]);
}

// pack [Wih; Whh] into per-(pair,chunk) blobs of fp16 mma B-fragments
__global__ void k_pack(const float* __restrict__ Wih, const float* __restrict__ Whh){
    int id = blockIdx.x*256 + threadIdx.x;
    const int TOTW = 64*NCHT*WBLOB;
    if (id >= TOTW) return;
    const int idx2 = id % WBLOB;
    const int lane = idx2 & 31;
    const int kl   = (idx2 >> 5) & 3;
    const int j    = (idx2 >> 7) & 1;
    const int nt   = idx2 >> 8;
    const int c    = (id / WBLOB) % NCHT;
    const int pair = id / (WBLOB*NCHT);
    const int tig = lane & 3;
    const int n = nt*DD + pair*16 + j*8 + (lane >> 2);
    const int k0 = c*64 + kl*16;
    int kk[4] = {k0+2*tig, k0+2*tig+1, k0+8+2*tig, k0+9+2*tig};
    unsigned q[4];
    #pragma unroll
    for (int i2=0;i2<4;i2++){
        int k = kk[i2];
        float w = (k < PP+EE) ? Wih[(size_t)k*G3 + n] : Whh[(size_t)(k-(PP+EE))*G3 + n];
        __half hb = __float2half_rn(w);
        q[i2] = *(unsigned short*)&hb;
    }
    g_Wf2[id] = make_uint2((q[1]<<16)|q[0], (q[3]<<16)|q[2]);
}

__global__ void k_stop(const float* __restrict__ Ws, const float* __restrict__ bs,
                       float* __restrict__ dout){
    const int w = (blockIdx.x*blockDim.x + threadIdx.x) >> 5;
    const int lane = threadIdx.x & 31;
    if (w >= TT*BB) return;
    const float* hrow = g_Hb + (size_t)w*DD;
    const float* crow = g_Cb + (size_t)w*EE;
    float acc = 0.f;
    for (int k = lane; k < DD; k += 32) acc += hrow[k]*Ws[k];
    for (int k = lane; k < EE; k += 32) acc += crow[k]*Ws[DD+k];
    #pragma unroll
    for (int o = 16; o > 0; o >>= 1) acc += __shfl_down_sync(0xffffffffu, acc, o);
    if (lane == 0){
        const int tq = w / BB, bq = w % BB;
        dout[(size_t)BB*TT*MM + (size_t)bq*TT + tq] = acc + bs[0];
    }
}

// ================= persistent decode kernel =================
__global__ void __launch_bounds__(TPB)
decode(const float* __restrict__ Wd,  const float* __restrict__ bd,
       const float* __restrict__ v,   const float* __restrict__ bv,
       const float* __restrict__ bih, const float* __restrict__ bhh,
       float* __restrict__ out)
{
    extern __shared__ float smf[];
    unsigned* smu = (unsigned*)smf;
    const unsigned sbase = (unsigned)__cvta_generic_to_shared(smf);
    const int blk = blockIdx.x, tid = threadIdx.x;
    const int lane = tid & 31, wq = tid >> 5;
    unsigned gen = g_rel;

    if (blk >= NB){
        for (int t = 0; t < TT; t++){ gsync(gen); psync(gen); gsync(gen); }
        return;
    }

    unsigned attGen = gen;
    const int pair = blk >> 1, ks = blk & 1;
    const uint2* Wsrc = g_Wf2 + (size_t)pair*NCHT*WBLOB;
    const int g = lane >> 2, tig = lane & 3;
    const int nt = wq >> 2;
    const int m0 = (wq & 3) * 16;
    const int c0h = 10 + ks*8;
    const int c0x = ks*5;

    // persistent smem: Wd rows, v, and ALL 13 W blobs (block-constant)
    for (int r = tid; r < 512; r += TPB)
        ((float4*)(smf + O_WDS))[r] = ((const float4*)(Wd + (size_t)blk*8*AA))[r];
    if (tid < 256) smf[O_VS + tid] = v[tid];
    if (tid < 384){
        for (int c2 = 0; c2 < 13; c2++){
            const int c = (c2 < 5) ? (c0x + c2) : (c0h + c2 - 5);
            cp16(sbase + (O_WP + c2*1536)*4 + (unsigned)tid*16,
                 (const uint4*)(Wsrc + (size_t)c*WBLOB) + tid);
        }
        CP_COMMIT();
        CPW(0);
    }
    __syncthreads();

    for (int t = 0; t < TT; t++){
        const int par = t & 1;
        float aX[2][4] = {}, aH[2][4] = {};

        // prefetch ALL 8 h-part A chunks (slots 0-7); consumed in phase 2
        if (wq < 12){
            #pragma unroll
            for (int i = 0; i < 8; i++)
                stage_A(sbase, i, 80 + (ks*8 + i)*8 + par*128, tid);
        }

        // ---------- phase 0: dpp reduce (all threads) ----------
        {
            float* part = smf + O_AWS;
            const int a = tid & 255, jh = tid >> 8;
            const float* pp = g_dpp + ((size_t)pair*NB + jh*64)*AA + a;
            float s = 0.f;
            #pragma unroll 16
            for (int j = 0; j < 64; j++) s += __ldcg(pp + (size_t)j*AA);
            part[tid] = s;
            __syncthreads();
            if (tid < 256) smf[O_DPS + tid] = part[tid] + part[256+tid] + bd[tid];
            __syncthreads();
        }
        // ---------- phase 1: scores (all threads) ----------
        {
            const int sl = tid >> 1, ah = tid & 1;
            const int s = ks*256 + sl;
            const uint4* ep4 = (const uint4*)(g_epH + ((size_t)(pair*SS + s))*AA + ah*128);
            const float* dp2 = smf + O_DPS + ah*128;
            const float* v2  = smf + O_VS  + ah*128;
            float acc = 0.f;
            #pragma unroll 4
            for (int q = 0; q < 16; q++){
                uint4 u = ep4[q];
                float2 f0 = __half22float2(*(__half2*)&u.x);
                float2 f1 = __half22float2(*(__half2*)&u.y);
                float2 f2 = __half22float2(*(__half2*)&u.z);
                float2 f3 = __half22float2(*(__half2*)&u.w);
                const int i0 = q*8;
                acc += v2[i0+0]*tanh_mufu(f0.x + dp2[i0+0]);
                acc += v2[i0+1]*tanh_mufu(f0.y + dp2[i0+1]);
                acc += v2[i0+2]*tanh_mufu(f1.x + dp2[i0+2]);
                acc += v2[i0+3]*tanh_mufu(f1.y + dp2[i0+3]);
                acc += v2[i0+4]*tanh_mufu(f2.x + dp2[i0+4]);
                acc += v2[i0+5]*tanh_mufu(f2.y + dp2[i0+5]);
                acc += v2[i0+6]*tanh_mufu(f3.x + dp2[i0+6]);
                acc += v2[i0+7]*tanh_mufu(f3.y + dp2[i0+7]);
            }
            acc += __shfl_xor_sync(0xffffffffu, acc, 1);
            if (ah == 0) g_sc[pair*SS + s] = acc + bv[0];
        }
        __syncthreads();
        // ---------- phase 2: concurrent [h-part MMA (12w) | softmax (4w)] ----------
        if (wq < 12){
            H_ITER(0, 7) H_ITER(1, 6) H_ITER(2, 5) H_ITER(3, 4)
            H_ITER(4, 3) H_ITER(5, 2) H_ITER(6, 1) H_ITER(7, 0)
        } else {
            const int tl = tid - 384;
            attGen++;
            BAR1;
            if (tl == 0){
                __threadfence();
                g_attf[blk*32] = attGen;
                while (g_attf[(blk^1)*32] < attGen) {}
                __threadfence();
            }
            BAR1;
            float* attr = smf + O_ATTR;
            float4 sc4 = *(const float4*)(g_sc + pair*SS + tl*4);
            float mx = fmaxf(fmaxf(sc4.x, sc4.y), fmaxf(sc4.z, sc4.w));
            #pragma unroll
            for (int o = 16; o; o >>= 1) mx = fmaxf(mx, __shfl_xor_sync(0xffffffffu, mx, o));
            if (lane == 0) attr[wq-12] = mx;
            BAR1;
            mx = fmaxf(fmaxf(attr[0], attr[1]), fmaxf(attr[2], attr[3]));
            float e0 = __expf(sc4.x - mx), e1 = __expf(sc4.y - mx);
            float e2 = __expf(sc4.z - mx), e3 = __expf(sc4.w - mx);
            float ss = e0 + e1 + e2 + e3;
            #pragma unroll
            for (int o = 16; o; o >>= 1) ss += __shfl_xor_sync(0xffffffffu, ss, o);
            if (lane == 0) attr[4 + (wq-12)] = ss;
            BAR1;
            const float inv = __fdividef(1.f, attr[4]+attr[5]+attr[6]+attr[7]);
            float4 av4 = make_float4(e0*inv, e1*inv, e2*inv, e3*inv);
            *(float4*)(smf + O_AWS + tl*4) = av4;
            if (ks == 0){
                *(float4*)(out + (size_t)BB*TT*MM + (size_t)BB*TT + ((size_t)pair*TT + t)*SS + tl*4) = av4;
                float pv = g_pre[((size_t)t*BB + pair)*PP + tl];
                g_Af[pair*KT2 + tl] = __float2half_rn(pv);
            }
        }
        __syncthreads();
        // ---------- phase 3: context (all threads; this block's ks half cols) ----------
        {
            const int ec = tid & 63, sq = tid >> 6;
            const uint2* eb = (const uint2*)(g_encH + ((size_t)(pair*SS + sq*64))*EE + ks*256 + ec*4);
            const float* awq = smf + O_AWS + sq*64;
            float c0 = 0.f, c1 = 0.f, c2 = 0.f, c3 = 0.f;
            #pragma unroll 8
            for (int s2 = 0; s2 < 64; s2++){
                uint2 u = __ldcg(eb + (size_t)s2*128);
                float a = awq[s2];
                float2 q0 = __half22float2(*(__half2*)&u.x);
                float2 q1 = __half22float2(*(__half2*)&u.y);
                c0 += a*q0.x; c1 += a*q0.y; c2 += a*q1.x; c3 += a*q1.y;
            }
            float* sm2 = smf + O_SM2;
            sm2[sq*256 + ec*4 + 0] = c0;
            sm2[sq*256 + ec*4 + 1] = c1;
            sm2[sq*256 + ec*4 + 2] = c2;
            sm2[sq*256 + ec*4 + 3] = c3;
            __syncthreads();
            if (tid < 256){
                float cc = 0.f;
                #pragma unroll
                for (int q = 0; q < 8; q++) cc += sm2[q*256 + tid];
                const int e2i = ks*256 + tid;
                g_Cb[((size_t)t*BB + pair)*EE + e2i] = cc;
                g_Af[pair*KT2 + PP + e2i] = __float2half_rn(cc);
            }
        }
        gsync(gen);
        // ---------- phase 4: x-part MMA (12w; A into slots 0-4) ----------
        if (wq < 12){
            #pragma unroll
            for (int j = 0; j < 5; j++)
                stage_A(sbase, j, (c0x + j)*8, tid);
            X_ITER(0, 4) X_ITER(1, 3) X_ITER(2, 2) X_ITER(3, 1) X_ITER(4, 0)
            // write gate partials [blk][plane][64][16]
            float* gp = g_gp + ((size_t)blk*4 + nt)*1024;
            #pragma unroll
            for (int j = 0; j < 2; j++){
                const int col = j*8 + 2*tig;
                gp[(m0+g)*16 + col]       = aX[j][0];
                gp[(m0+g)*16 + col + 1]   = aX[j][1];
                gp[(m0+g+8)*16 + col]     = aX[j][2];
                gp[(m0+g+8)*16 + col + 1] = aX[j][3];
            }
            if (nt == 2){
                float* gp3 = g_gp + ((size_t)blk*4 + 3)*1024;
                #pragma unroll
                for (int j = 0; j < 2; j++){
                    const int col = j*8 + 2*tig;
                    gp3[(m0+g)*16 + col]       = aH[j][0];
                    gp3[(m0+g)*16 + col + 1]   = aH[j][1];
                    gp3[(m0+g+8)*16 + col]     = aH[j][2];
                    gp3[(m0+g+8)*16 + col + 1] = aH[j][3];
                }
            }
        }
        psync(gen);
        // ---------- phase 5: GRU pointwise + dp k-partials ----------
        {
            float* Wds = smf + O_WDS; float* hs = smf + O_HS;
            {
                const int b = tid >> 3, dl = tid & 7, d = blk*8 + dl;
                const int cd = ks*8 + dl;
                const int o = b*16 + cd;
                const float* gpA = g_gp + (size_t)(pair*2)*4096;
                const float* gpB = gpA + 4096;
                float gr  = gpA[o]        + gpB[o]        + bih[d]      + bhh[d];
                float gz  = gpA[1024 + o] + gpB[1024 + o] + bih[DD+d]   + bhh[DD+d];
                float gin = gpA[2048 + o] + gpB[2048 + o] + bih[2*DD+d];
                float ghn = gpA[3072 + o] + gpB[3072 + o] + bhh[2*DD+d];
                float r = fsig(gr), z = fsig(gz);
                float n = ftanh(gin + r*ghn);
                float h = g_h[b*DD + d];
                float hn = (1.f - z)*n + z*h;
                g_h[b*DD + d] = hn;
                g_Hb[((size_t)t*BB + b)*DD + d] = hn;
                const int hoff = PP+EE + ((t+1)&1)*DD + d;
                g_Af[b*KT2 + hoff] = __float2half_rn(hn);
                hs[b*8 + dl] = hn;
            }
            __syncthreads();
            {
                const int bg = tid >> 5, ag = tid & 31;
                const int b4 = bg*4, a8 = ag*8;
                float acc[4][8] = {};
                #pragma unroll
                for (int kk = 0; kk < 8; kk++){
                    const float4 w0 = *(const float4*)(Wds + kk*256 + a8);
                    const float4 w1 = *(const float4*)(Wds + kk*256 + a8 + 4);
                    #pragma unroll
                    for (int i = 0; i < 4; i++){
                        const float h = hs[(b4+i)*8 + kk];
                        acc[i][0]+=h*w0.x; acc[i][1]+=h*w0.y; acc[i][2]+=h*w0.z; acc[i][3]+=h*w0.w;
                        acc[i][4]+=h*w1.x; acc[i][5]+=h*w1.y; acc[i][6]+=h*w1.z; acc[i][7]+=h*w1.w;
                    }
                }
                #pragma unroll
                for (int i = 0; i < 4; i++){
                    float* o = g_dpp + ((size_t)(b4+i)*NB + blk)*AA + a8;
                    *(float4*)(o)   = make_float4(acc[i][0],acc[i][1],acc[i][2],acc[i][3]);
                    *(float4*)(o+4) = make_float4(acc[i][4],acc[i][5],acc[i][6],acc[i][7]);
                }
            }
        }
        gsync(gen);
    }
}

// ---------------- host ----------------
extern "C" void kernel_launch(void* const* d_in, const int* in_sizes, int n_in,
                              void* d_out, int out_size){
    const float* enc = (const float*)d_in[0];
    const float* tm  = (const float*)d_in[1];
    const float* We  = (const float*)d_in[2];
    const float* be  = (const float*)d_in[3];
    const float* Wd  = (const float*)d_in[4];
    const float* bd  = (const float*)d_in[5];
    const float* v   = (const float*)d_in[6];
    const float* bv  = (const float*)d_in[7];
    const float* W1  = (const float*)d_in[8];
    const float* b1  = (const float*)d_in[9];
    const float* W2  = (const float*)d_in[10];
    const float* b2  = (const float*)d_in[11];
    const float* Wih = (const float*)d_in[12];
    const float* bih = (const float*)d_in[13];
    const float* Whh = (const float*)d_in[14];
    const float* bhh = (const float*)d_in[15];
    const float* Wo  = (const float*)d_in[16];
    const float* bo  = (const float*)d_in[17];
    const float* Ws  = (const float*)d_in[18];
    const float* bs  = (const float*)d_in[19];
    float* out = (float*)d_out;

    float *p_prev, *p_ph, *p_pre, *p_Hb, *p_Cb; __half *p_epH;
    cudaGetSymbolAddress((void**)&p_epH,  g_epH);
    cudaGetSymbolAddress((void**)&p_prev, g_prev);
    cudaGetSymbolAddress((void**)&p_ph,   g_ph);
    cudaGetSymbolAddress((void**)&p_pre,  g_pre);
    cudaGetSymbolAddress((void**)&p_Hb,   g_Hb);
    cudaGetSymbolAddress((void**)&p_Cb,   g_Cb);

    cudaFuncSetAttribute(decode, cudaFuncAttributeMaxDynamicSharedMemorySize, SMEM_WORDS*4);

    // precompute
    k_init<<<(BB*NB*AA + 255)/256, 256>>>();
    k_prev<<<(TT*BB*MM + 255)/256, 256>>>(tm);
    k_convE<<<(BB*SS*EE + 255)/256, 256>>>(enc);
    k_pack<<<(64*NCHT*WBLOB + 255)/256, 256>>>(Wih, Whh);
    sgemm<<<dim3(HP/64, (TT*BB)/64), 256>>>(p_prev, W1, b1, p_ph,  TT*BB, HP, MM, 1, 0, 0);
    sgemm<<<dim3(PP/64, (TT*BB)/64), 256>>>(p_ph,   W2, b2, p_pre, TT*BB, PP, HP, 1, 0, 0);
    sgemm<<<dim3(AA/64, (BB*SS)/64), 256>>>(enc,    We, be, (float*)p_epH, BB*SS, AA, EE, 4, 0, 0);

    // sequential decode: one persistent kernel
    decode<<<NBL, TPB, SMEM_WORDS*4>>>(Wd, bd, v, bv, bih, bhh, out);

    // output heads
    sgemm<<<dim3(MM/64, (TT*BB)/64), 256>>>(p_Hb, Wo,           bo,      out, TT*BB, MM, DD, 0, BB, TT);
    sgemm<<<dim3(MM/64, (TT*BB)/64), 256>>>(p_Cb, Wo + DD*MM,   nullptr, out, TT*BB, MM, EE, 2, BB, TT);
    k_stop<<<(TT*BB)/8, 256>>>(Ws, bs, out);
}

// round 14
// speedup vs baseline: 1.0066x; 1.0066x over previous
#include <cuda_runtime.h>
#include <cuda_bf16.h>
#include <cuda_fp16.h>

#define BB 64
#define SS 512
#define EE 512
#define AA 256
#define HP 256
#define PP 128
#define DD 1024
#define MM 128
#define TT 800
#define G3 3072
#define NB 128
#define NBL 148
#define TPB 512
#define KT2 2688
#define NCHT 26
#define WBLOB 768          /* uint2 per W chunk blob (fp16) */

// dynamic smem layout (float words)
#define O_WP  0                         /* 13 resident W blobs: 13*1536 */
#define O_A   19968                     /* 8 A slots: 8*2304 */
#define O_DPS 38400
#define O_VS  38656
#define O_AWS 38912
#define O_ATTR 39424
#define O_SM2 39488
#define O_WDS 41536
#define O_HS  43584
#define SMEM_WORDS 44096                /* 176,384 bytes */

// ---------------- static scratch ----------------
__device__ __align__(128) __half g_epH[BB*SS*AA];
__device__ __align__(128) __half g_encH[BB*SS*EE];
__device__ __align__(128) float g_prev[TT*BB*MM];
__device__ __align__(128) float g_ph  [TT*BB*HP];
__device__ __align__(128) float g_pre [TT*BB*PP];
__device__ __align__(128) float g_h   [BB*DD];
__device__ __align__(128) float g_sc  [BB*SS];
__device__ __align__(128) float g_dpp [BB*NB*AA];
__device__ __align__(128) __half g_Af [BB*KT2];
__device__ __align__(128) uint2 g_Wf2[(size_t)64*NCHT*WBLOB];
__device__ __align__(128) float g_gp  [NB*4*64*16];
__device__ __align__(128) float g_Hb  [(size_t)TT*BB*DD];
__device__ __align__(128) float g_Cb  [(size_t)TT*BB*EE];
__device__ __align__(128) volatile unsigned g_flags[NBL*32];
__device__ __align__(128) volatile unsigned g_pairf[NBL*32];
__device__ __align__(128) volatile unsigned g_attf[NB*32];
__device__ volatile unsigned g_rel;

__device__ __forceinline__ float fsig(float x){
    float e = __expf(-x);
    return __fdividef(1.f, 1.f + e);
}
__device__ __forceinline__ float ftanh(float x){
    x = fminf(fmaxf(x, -15.f), 15.f);
    float e = __expf(2.f*x);
    return __fdividef(e - 1.f, e + 1.f);
}
__device__ __forceinline__ float tanh_mufu(float x){
    float y; asm("tanh.approx.f32 %0, %1;" : "=f"(y) : "f"(x)); return y;
}

__device__ __forceinline__ void gsync(unsigned &gen){
    gen++;
    __syncthreads();
    const int tid = threadIdx.x;
    if (blockIdx.x == 0){
        if (tid > 0 && tid < NBL){
            while (g_flags[tid*32] < gen) {}
        }
        __syncthreads();
        if (tid == 0){ __threadfence(); g_rel = gen; }
    } else {
        if (tid == 0){
            __threadfence();
            g_flags[blockIdx.x*32] = gen;
            while (g_rel < gen) {}
            __threadfence();
        }
    }
    __syncthreads();
}

__device__ __forceinline__ void psync(unsigned &gen){
    gen++;
    __syncthreads();
    if (threadIdx.x == 0){
        __threadfence();
        g_pairf[blockIdx.x*32] = gen;
        while (g_pairf[(blockIdx.x^1)*32] < gen) {}
        __threadfence();
    }
    __syncthreads();
}

#define BAR1 asm volatile("bar.sync 1, 128;" ::: "memory")
#define BAR2 asm volatile("bar.sync 2, 384;" ::: "memory")

__device__ __forceinline__ void cp16(unsigned dst, const void* src){
    asm volatile("cp.async.cg.shared.global [%0], [%1], 16;" :: "r"(dst), "l"(src) : "memory");
}
#define CP_COMMIT() asm volatile("cp.async.commit_group;" ::: "memory")
#define CPW(n) asm volatile("cp.async.wait_group " #n ";" ::: "memory")

#define MMA(D0,D1,D2,D3,A0,A1,A2,A3,B0,B1) \
    asm volatile("mma.sync.aligned.m16n8k16.row.col.f32.f16.f16.f32 " \
        "{%0,%1,%2,%3},{%4,%5,%6,%7},{%8,%9},{%0,%1,%2,%3};" \
        : "+f"(D0),"+f"(D1),"+f"(D2),"+f"(D3) \
        : "r"(A0),"r"(A1),"r"(A2),"r"(A3),"r"(B0),"r"(B1))

#define DO_MMA(ACC, slot, wslot) { \
    const unsigned* A32 = smu + O_A + (slot)*2304; \
    const uint2* Wq = (const uint2*)(smu + O_WP + (wslot)*1536) + nt*256; \
    _Pragma("unroll") \
    for (int kl = 0; kl < 4; kl++){ \
        const int r0 = (m0+g)*36 + kl*8 + tig; \
        unsigned a0 = A32[r0],   a1 = A32[r0+288]; \
        unsigned a2 = A32[r0+4], a3 = A32[r0+292]; \
        _Pragma("unroll") \
        for (int j = 0; j < 2; j++){ \
            uint2 bw = Wq[j*128 + kl*32 + lane]; \
            MMA(ACC[j][0],ACC[j][1],ACC[j][2],ACC[j][3], a0,a1,a2,a3, bw.x,bw.y); \
        } \
    } }

#define H2(i) { if (nt == 2){ DO_MMA(aH, (i), 5+(i)); } else { DO_MMA(aX, (i), 5+(i)); } }

#define X_ITER(j, WLIT) { \
    CPW(WLIT); \
    BAR2; \
    DO_MMA(aX, (j), (j)); }

// stage one chunk's A plane (8KB) into slot; called by warps 0-11 (384 threads)
__device__ __forceinline__ void stage_A(unsigned sbase, int slot, int idx4, int tid){
    #pragma unroll
    for (int k = 0; k < 2; k++){
        int idx = tid + k*384;
        if (idx < 512){
            int row = idx >> 3, col = idx & 7;
            cp16(sbase + (O_A + slot*2304 + (row*9+col)*4)*4,
                 (const uint4*)g_Af + row*336 + idx4 + col);
        }
    }
    CP_COMMIT();
}

// ---------------- generic tiled SGEMM (pre/epilogue only) ----------------
#define BKK 16
__global__ void sgemm(const float* __restrict__ A, const float* __restrict__ B,
                      const float* __restrict__ bias, float* __restrict__ C,
                      int M, int N, int K, int flags, int Bdim, int Tdim)
{
    __shared__ float As[BKK][64];
    __shared__ float Bs[BKK][64];
    const int n0 = blockIdx.x * 64;
    const int m0 = blockIdx.y * 64;
    const int tid = threadIdx.x;
    const int tx = tid & 15;
    const int ty = tid >> 4;
    float acc[4][4] = {};
    const int arow  = tid >> 2;
    const int acol4 = (tid & 3) * 4;
    const int brow  = tid >> 4;
    const int bcol4 = (tid & 15) * 4;

    for (int k = 0; k < K; k += BKK) {
        float4 av = *(const float4*)(A + (size_t)(m0 + arow) * K + k + acol4);
        As[acol4+0][arow] = av.x;
        As[acol4+1][arow] = av.y;
        As[acol4+2][arow] = av.z;
        As[acol4+3][arow] = av.w;
        float4 bvv = *(const float4*)(B + (size_t)(k + brow) * N + n0 + bcol4);
        *(float4*)(&Bs[brow][bcol4]) = bvv;
        __syncthreads();
        #pragma unroll
        for (int kk = 0; kk < BKK; kk++) {
            float4 a4 = *(const float4*)(&As[kk][ty*4]);
            float4 b4 = *(const float4*)(&Bs[kk][tx*4]);
            acc[0][0] += a4.x*b4.x; acc[0][1] += a4.x*b4.y; acc[0][2] += a4.x*b4.z; acc[0][3] += a4.x*b4.w;
            acc[1][0] += a4.y*b4.x; acc[1][1] += a4.y*b4.y; acc[1][2] += a4.y*b4.z; acc[1][3] += a4.y*b4.w;
            acc[2][0] += a4.z*b4.x; acc[2][1] += a4.z*b4.y; acc[2][2] += a4.z*b4.z; acc[2][3] += a4.z*b4.w;
            acc[3][0] += a4.w*b4.x; acc[3][1] += a4.w*b4.y; acc[3][2] += a4.w*b4.z; acc[3][3] += a4.w*b4.w;
        }
        __syncthreads();
    }
    #pragma unroll
    for (int i = 0; i < 4; i++) {
        const int m = m0 + ty*4 + i;
        #pragma unroll
        for (int j = 0; j < 4; j++) {
            const int n = n0 + tx*4 + j;
            float val = acc[i][j];
            if (bias) val += bias[n];
            if (flags & 1) val = fmaxf(val, 0.f);
            size_t idx;
            if (Bdim > 0) {
                const int bq = m % Bdim, tq = m / Bdim;
                idx = ((size_t)bq * Tdim + tq) * N + n;
            } else {
                idx = (size_t)m * N + n;
            }
            if (flags & 4)      ((__half*)C)[idx] = __float2half_rn(val);
            else if (flags & 2) C[idx] += val;
            else                C[idx] = val;
        }
    }
}

__global__ void k_init(){
    int i = blockIdx.x*256 + threadIdx.x;
    if (i < BB*NB*AA) g_dpp[i] = 0.f;
    if (i < BB*KT2) g_Af[i] = __float2half_rn(0.f);
    if (i < BB*DD) g_h[i] = 0.f;
}

__global__ void k_prev(const float* __restrict__ tm){
    int i = blockIdx.x*256 + threadIdx.x;
    if (i >= TT*BB*MM) return;
    int m  = i & (MM-1);
    int tb = i >> 7;
    int b  = tb & (BB-1);
    int t  = tb >> 6;
    g_prev[i] = (t == 0) ? 0.f : tm[((size_t)b*TT + (t-1))*MM + m];
}

__global__ void k_convE(const float* __restrict__ enc){
    int i = blockIdx.x*256 + threadIdx.x;
    if (i < BB*SS*EE) g_encH[i] = __float2half_rn(enc[i]);
}

// pack [Wih; Whh] into per-(pair,chunk) blobs of fp16 mma B-fragments
__global__ void k_pack(const float* __restrict__ Wih, const float* __restrict__ Whh){
    int id = blockIdx.x*256 + threadIdx.x;
    const int TOTW = 64*NCHT*WBLOB;
    if (id >= TOTW) return;
    const int idx2 = id % WBLOB;
    const int lane = idx2 & 31;
    const int kl   = (idx2 >> 5) & 3;
    const int j    = (idx2 >> 7) & 1;
    const int nt   = idx2 >> 8;
    const int c    = (id / WBLOB) % NCHT;
    const int pair = id / (WBLOB*NCHT);
    const int tig = lane & 3;
    const int n = nt*DD + pair*16 + j*8 + (lane >> 2);
    const int k0 = c*64 + kl*16;
    int kk[4] = {k0+2*tig, k0+2*tig+1, k0+8+2*tig, k0+9+2*tig};
    unsigned q[4];
    #pragma unroll
    for (int i2=0;i2<4;i2++){
        int k = kk[i2];
        float w = (k < PP+EE) ? Wih[(size_t)k*G3 + n] : Whh[(size_t)(k-(PP+EE))*G3 + n];
        __half hb = __float2half_rn(w);
        q[i2] = *(unsigned short*)&hb;
    }
    g_Wf2[id] = make_uint2((q[1]<<16)|q[0], (q[3]<<16)|q[2]);
}

__global__ void k_stop(const float* __restrict__ Ws, const float* __restrict__ bs,
                       float* __restrict__ dout){
    const int w = (blockIdx.x*blockDim.x + threadIdx.x) >> 5;
    const int lane = threadIdx.x & 31;
    if (w >= TT*BB) return;
    const float* hrow = g_Hb + (size_t)w*DD;
    const float* crow = g_Cb + (size_t)w*EE;
    float acc = 0.f;
    for (int k = lane; k < DD; k += 32) acc += hrow[k]*Ws[k];
    for (int k = lane; k < EE; k += 32) acc += crow[k]*Ws[DD+k];
    #pragma unroll
    for (int o = 16; o > 0; o >>= 1) acc += __shfl_down_sync(0xffffffffu, acc, o);
    if (lane == 0){
        const int tq = w / BB, bq = w % BB;
        dout[(size_t)BB*TT*MM + (size_t)bq*TT + tq] = acc + bs[0];
    }
}

// ================= persistent decode kernel =================
__global__ void __launch_bounds__(TPB)
decode(const float* __restrict__ Wd,  const float* __restrict__ bd,
       const float* __restrict__ v,   const float* __restrict__ bv,
       const float* __restrict__ bih, const float* __restrict__ bhh,
       float* __restrict__ out)
{
    extern __shared__ float smf[];
    unsigned* smu = (unsigned*)smf;
    const unsigned sbase = (unsigned)__cvta_generic_to_shared(smf);
    const int blk = blockIdx.x, tid = threadIdx.x;
    const int lane = tid & 31, wq = tid >> 5;
    unsigned gen = g_rel;

    if (blk >= NB){
        for (int t = 0; t < TT; t++){ gsync(gen); psync(gen); gsync(gen); }
        return;
    }

    unsigned attGen = gen;
    const int pair = blk >> 1, ks = blk & 1;
    const uint2* Wsrc = g_Wf2 + (size_t)pair*NCHT*WBLOB;
    const int g = lane >> 2, tig = lane & 3;
    const int nt = wq >> 2;
    const int m0 = (wq & 3) * 16;
    const int c0h = 10 + ks*8;
    const int c0x = ks*5;

    // persistent smem: Wd rows, v, and ALL 13 W blobs (block-constant)
    for (int r = tid; r < 512; r += TPB)
        ((float4*)(smf + O_WDS))[r] = ((const float4*)(Wd + (size_t)blk*8*AA))[r];
    if (tid < 256) smf[O_VS + tid] = v[tid];
    if (tid < 384){
        for (int c2 = 0; c2 < 13; c2++){
            const int c = (c2 < 5) ? (c0x + c2) : (c0h + c2 - 5);
            cp16(sbase + (O_WP + c2*1536)*4 + (unsigned)tid*16,
                 (const uint4*)(Wsrc + (size_t)c*WBLOB) + tid);
        }
        CP_COMMIT();
        CPW(0);
    }
    __syncthreads();

    for (int t = 0; t < TT; t++){
        const int par = t & 1;
        float aX[2][4] = {}, aH[2][4] = {};

        // prefetch ALL 8 h-part A chunks (slots 0-7); consumed in phase 2
        if (wq < 12){
            #pragma unroll
            for (int i = 0; i < 8; i++)
                stage_A(sbase, i, 80 + (ks*8 + i)*8 + par*128, tid);
        }

        // ---------- phase 0: dpp reduce (all threads) ----------
        {
            float* part = smf + O_AWS;
            const int a = tid & 255, jh = tid >> 8;
            const float* pp = g_dpp + ((size_t)pair*NB + jh*64)*AA + a;
            float s = 0.f;
            #pragma unroll 16
            for (int j = 0; j < 64; j++) s += __ldcg(pp + (size_t)j*AA);
            part[tid] = s;
            __syncthreads();
            if (tid < 256) smf[O_DPS + tid] = part[tid] + part[256+tid] + bd[tid];
            __syncthreads();
        }
        // ---------- phase 1: scores (all threads) ----------
        {
            const int sl = tid >> 1, ah = tid & 1;
            const int s = ks*256 + sl;
            const uint4* ep4 = (const uint4*)(g_epH + ((size_t)(pair*SS + s))*AA + ah*128);
            const float* dp2 = smf + O_DPS + ah*128;
            const float* v2  = smf + O_VS  + ah*128;
            float acc = 0.f;
            #pragma unroll 4
            for (int q = 0; q < 16; q++){
                uint4 u = ep4[q];
                float2 f0 = __half22float2(*(__half2*)&u.x);
                float2 f1 = __half22float2(*(__half2*)&u.y);
                float2 f2 = __half22float2(*(__half2*)&u.z);
                float2 f3 = __half22float2(*(__half2*)&u.w);
                const int i0 = q*8;
                acc += v2[i0+0]*tanh_mufu(f0.x + dp2[i0+0]);
                acc += v2[i0+1]*tanh_mufu(f0.y + dp2[i0+1]);
                acc += v2[i0+2]*tanh_mufu(f1.x + dp2[i0+2]);
                acc += v2[i0+3]*tanh_mufu(f1.y + dp2[i0+3]);
                acc += v2[i0+4]*tanh_mufu(f2.x + dp2[i0+4]);
                acc += v2[i0+5]*tanh_mufu(f2.y + dp2[i0+5]);
                acc += v2[i0+6]*tanh_mufu(f3.x + dp2[i0+6]);
                acc += v2[i0+7]*tanh_mufu(f3.y + dp2[i0+7]);
            }
            acc += __shfl_xor_sync(0xffffffffu, acc, 1);
            if (ah == 0) g_sc[pair*SS + s] = acc + bv[0];
        }
        __syncthreads();
        // ---------- phase 2: concurrent [h-part MMA (12w) | softmax (4w)] ----------
        if (wq < 12){
            CPW(0);
            BAR2;
            H2(0) H2(1) H2(2) H2(3) H2(4) H2(5) H2(6) H2(7)
        } else {
            const int tl = tid - 384;
            attGen++;
            BAR1;
            if (tl == 0){
                __threadfence();
                g_attf[blk*32] = attGen;
                while (g_attf[(blk^1)*32] < attGen) {}
                __threadfence();
            }
            BAR1;
            float* attr = smf + O_ATTR;
            float4 sc4 = *(const float4*)(g_sc + pair*SS + tl*4);
            float mx = fmaxf(fmaxf(sc4.x, sc4.y), fmaxf(sc4.z, sc4.w));
            #pragma unroll
            for (int o = 16; o; o >>= 1) mx = fmaxf(mx, __shfl_xor_sync(0xffffffffu, mx, o));
            if (lane == 0) attr[wq-12] = mx;
            BAR1;
            mx = fmaxf(fmaxf(attr[0], attr[1]), fmaxf(attr[2], attr[3]));
            float e0 = __expf(sc4.x - mx), e1 = __expf(sc4.y - mx);
            float e2 = __expf(sc4.z - mx), e3 = __expf(sc4.w - mx);
            float ss = e0 + e1 + e2 + e3;
            #pragma unroll
            for (int o = 16; o; o >>= 1) ss += __shfl_xor_sync(0xffffffffu, ss, o);
            if (lane == 0) attr[4 + (wq-12)] = ss;
            BAR1;
            const float inv = __fdividef(1.f, attr[4]+attr[5]+attr[6]+attr[7]);
            float4 av4 = make_float4(e0*inv, e1*inv, e2*inv, e3*inv);
            *(float4*)(smf + O_AWS + tl*4) = av4;
            if (ks == 0){
                *(float4*)(out + (size_t)BB*TT*MM + (size_t)BB*TT + ((size_t)pair*TT + t)*SS + tl*4) = av4;
                float pv = g_pre[((size_t)t*BB + pair)*PP + tl];
                g_Af[pair*KT2 + tl] = __float2half_rn(pv);
            }
        }
        __syncthreads();
        // ---------- phase 3: context (all threads; this block's ks half cols) ----------
        {
            const int ec = tid & 63, sq = tid >> 6;
            const uint2* eb = (const uint2*)(g_encH + ((size_t)(pair*SS + sq*64))*EE + ks*256 + ec*4);
            const float* awq = smf + O_AWS + sq*64;
            float c0 = 0.f, c1 = 0.f, c2 = 0.f, c3 = 0.f;
            #pragma unroll 8
            for (int s2 = 0; s2 < 64; s2++){
                uint2 u = __ldcg(eb + (size_t)s2*128);
                float a = awq[s2];
                float2 q0 = __half22float2(*(__half2*)&u.x);
                float2 q1 = __half22float2(*(__half2*)&u.y);
                c0 += a*q0.x; c1 += a*q0.y; c2 += a*q1.x; c3 += a*q1.y;
            }
            float* sm2 = smf + O_SM2;
            sm2[sq*256 + ec*4 + 0] = c0;
            sm2[sq*256 + ec*4 + 1] = c1;
            sm2[sq*256 + ec*4 + 2] = c2;
            sm2[sq*256 + ec*4 + 3] = c3;
            __syncthreads();
            if (tid < 256){
                float cc = 0.f;
                #pragma unroll
                for (int q = 0; q < 8; q++) cc += sm2[q*256 + tid];
                const int e2i = ks*256 + tid;
                g_Cb[((size_t)t*BB + pair)*EE + e2i] = cc;
                g_Af[pair*KT2 + PP + e2i] = __float2half_rn(cc);
            }
        }
        gsync(gen);
        // ---------- phase 4: x-part MMA (12w; A into slots 0-4) ----------
        if (wq < 12){
            #pragma unroll
            for (int j = 0; j < 5; j++)
                stage_A(sbase, j, (c0x + j)*8, tid);
            X_ITER(0, 4) X_ITER(1, 3) X_ITER(2, 2) X_ITER(3, 1) X_ITER(4, 0)
            // write gate partials [blk][plane][64][16]
            float* gp = g_gp + ((size_t)blk*4 + nt)*1024;
            #pragma unroll
            for (int j = 0; j < 2; j++){
                const int col = j*8 + 2*tig;
                gp[(m0+g)*16 + col]       = aX[j][0];
                gp[(m0+g)*16 + col + 1]   = aX[j][1];
                gp[(m0+g+8)*16 + col]     = aX[j][2];
                gp[(m0+g+8)*16 + col + 1] = aX[j][3];
            }
            if (nt == 2){
                float* gp3 = g_gp + ((size_t)blk*4 + 3)*1024;
                #pragma unroll
                for (int j = 0; j < 2; j++){
                    const int col = j*8 + 2*tig;
                    gp3[(m0+g)*16 + col]       = aH[j][0];
                    gp3[(m0+g)*16 + col + 1]   = aH[j][1];
                    gp3[(m0+g+8)*16 + col]     = aH[j][2];
                    gp3[(m0+g+8)*16 + col + 1] = aH[j][3];
                }
            }
        }
        psync(gen);
        // ---------- phase 5: GRU pointwise + dp k-partials ----------
        {
            float* Wds = smf + O_WDS; float* hs = smf + O_HS;
            {
                const int b = tid >> 3, dl = tid & 7, d = blk*8 + dl;
                const int cd = ks*8 + dl;
                const int o = b*16 + cd;
                const float* gpA = g_gp + (size_t)(pair*2)*4096;
                const float* gpB = gpA + 4096;
                float gr  = gpA[o]        + gpB[o]        + bih[d]      + bhh[d];
                float gz  = gpA[1024 + o] + gpB[1024 + o] + bih[DD+d]   + bhh[DD+d];
                float gin = gpA[2048 + o] + gpB[2048 + o] + bih[2*DD+d];
                float ghn = gpA[3072 + o] + gpB[3072 + o] + bhh[2*DD+d];
                float r = fsig(gr), z = fsig(gz);
                float n = ftanh(gin + r*ghn);
                float h = g_h[b*DD + d];
                float hn = (1.f - z)*n + z*h;
                g_h[b*DD + d] = hn;
                g_Hb[((size_t)t*BB + b)*DD + d] = hn;
                const int hoff = PP+EE + ((t+1)&1)*DD + d;
                g_Af[b*KT2 + hoff] = __float2half_rn(hn);
                hs[b*8 + dl] = hn;
            }
            __syncthreads();
            {
                const int bg = tid >> 5, ag = tid & 31;
                const int b4 = bg*4, a8 = ag*8;
                float acc[4][8] = {};
                #pragma unroll
                for (int kk = 0; kk < 8; kk++){
                    const float4 w0 = *(const float4*)(Wds + kk*256 + a8);
                    const float4 w1 = *(const float4*)(Wds + kk*256 + a8 + 4);
                    #pragma unroll
                    for (int i = 0; i < 4; i++){
                        const float h = hs[(b4+i)*8 + kk];
                        acc[i][0]+=h*w0.x; acc[i][1]+=h*w0.y; acc[i][2]+=h*w0.z; acc[i][3]+=h*w0.w;
                        acc[i][4]+=h*w1.x; acc[i][5]+=h*w1.y; acc[i][6]+=h*w1.z; acc[i][7]+=h*w1.w;
                    }
                }
                #pragma unroll
                for (int i = 0; i < 4; i++){
                    float* o = g_dpp + ((size_t)(b4+i)*NB + blk)*AA + a8;
                    *(float4*)(o)   = make_float4(acc[i][0],acc[i][1],acc[i][2],acc[i][3]);
                    *(float4*)(o+4) = make_float4(acc[i][4],acc[i][5],acc[i][6],acc[i][7]);
                }
            }
        }
        gsync(gen);
    }
}

// ---------------- host ----------------
extern "C" void kernel_launch(void* const* d_in, const int* in_sizes, int n_in,
                              void* d_out, int out_size){
    const float* enc = (const float*)d_in[0];
    const float* tm  = (const float*)d_in[1];
    const float* We  = (const float*)d_in[2];
    const float* be  = (const float*)d_in[3];
    const float* Wd  = (const float*)d_in[4];
    const float* bd  = (const float*)d_in[5];
    const float* v   = (const float*)d_in[6];
    const float* bv  = (const float*)d_in[7];
    const float* W1  = (const float*)d_in[8];
    const float* b1  = (const float*)d_in[9];
    const float* W2  = (const float*)d_in[10];
    const float* b2  = (const float*)d_in[11];
    const float* Wih = (const float*)d_in[12];
    const float* bih = (const float*)d_in[13];
    const float* Whh = (const float*)d_in[14];
    const float* bhh = (const float*)d_in[15];
    const float* Wo  = (const float*)d_in[16];
    const float* bo  = (const float*)d_in[17];
    const float* Ws  = (const float*)d_in[18];
    const float* bs  = (const float*)d_in[19];
    float* out = (float*)d_out;

    float *p_prev, *p_ph, *p_pre, *p_Hb, *p_Cb; __half *p_epH;
    cudaGetSymbolAddress((void**)&p_epH,  g_epH);
    cudaGetSymbolAddress((void**)&p_prev, g_prev);
    cudaGetSymbolAddress((void**)&p_ph,   g_ph);
    cudaGetSymbolAddress((void**)&p_pre,  g_pre);
    cudaGetSymbolAddress((void**)&p_Hb,   g_Hb);
    cudaGetSymbolAddress((void**)&p_Cb,   g_Cb);

    cudaFuncSetAttribute(decode, cudaFuncAttributeMaxDynamicSharedMemorySize, SMEM_WORDS*4);

    // precompute
    k_init<<<(BB*NB*AA + 255)/256, 256>>>();
    k_prev<<<(TT*BB*MM + 255)/256, 256>>>(tm);
    k_convE<<<(BB*SS*EE + 255)/256, 256>>>(enc);
    k_pack<<<(64*NCHT*WBLOB + 255)/256, 256>>>(Wih, Whh);
    sgemm<<<dim3(HP/64, (TT*BB)/64), 256>>>(p_prev, W1, b1, p_ph,  TT*BB, HP, MM, 1, 0, 0);
    sgemm<<<dim3(PP/64, (TT*BB)/64), 256>>>(p_ph,   W2, b2, p_pre, TT*BB, PP, HP, 1, 0, 0);
    sgemm<<<dim3(AA/64, (BB*SS)/64), 256>>>(enc,    We, be, (float*)p_epH, BB*SS, AA, EE, 4, 0, 0);

    // sequential decode: one persistent kernel
    decode<<<NBL, TPB, SMEM_WORDS*4>>>(Wd, bd, v, bv, bih, bhh, out);

    // output heads
    sgemm<<<dim3(MM/64, (TT*BB)/64), 256>>>(p_Hb, Wo,           bo,      out, TT*BB, MM, DD, 0, BB, TT);
    sgemm<<<dim3(MM/64, (TT*BB)/64), 256>>>(p_Cb, Wo + DD*MM,   nullptr, out, TT*BB, MM, EE, 2, BB, TT);
    k_stop<<<(TT*BB)/8, 256>>>(Ws, bs, out);
}